// round 2
// baseline (speedup 1.0000x reference)
#include <cuda_runtime.h>

// ComponentWiseSpline: fused single-kernel rational-quadratic spline flow.
// B=65536 rows, D=128 dims, K=8 bins.
// Each block builds its own precombined smem table (48KB, bank-conflict-free
// [k][c][lane] layout, 12-float records), each lane owns 4 consecutive dims
// with thresholds register-resident, float4 global I/O, warp-per-row reduce.

#define BB 65536
#define DD 128
#define KK 8

#define WARPS 8
#define RPW   14                       // rows per warp
#define ROWS_PER_BLOCK (WARPS * RPW)   // 112
#define NBLOCKS ((BB + ROWS_PER_BLOCK - 1) / ROWS_PER_BLOCK)  // 586

// record: {invW, -cw*invW, cumH, H*delta, H*d0, e=d0+d1-2delta, delta,
//          c1=d1*delta^2, c2=2*delta^3, c3=d0*delta^2, thr(cw[k+1]+EPS), pad}
#define RSZ 12

__global__ void __launch_bounds__(256, 4)
spline_kernel(const float* __restrict__ x,
              const float* __restrict__ uw,
              const float* __restrict__ uh,
              const float* __restrict__ ud,
              float* __restrict__ uout,
              float* __restrict__ ldout) {
    __shared__ float sT[KK * DD * RSZ];   // 49152 bytes

    const int tid  = threadIdx.x;
    const int lane = tid & 31;
    const int warp = tid >> 5;

    // ---- per-block table build (threads 0..127, one per dim) ----
    if (tid < DD) {
        const int d = tid;
        const float BOUND = 3.0f;
        const float MINW = 1e-3f, MINH = 1e-3f, MIND = 1e-3f, EPS = 1e-6f;

        float w[KK], h[KK];
        float m = -1e30f;
        #pragma unroll
        for (int k = 0; k < KK; k++) { w[k] = uw[d * KK + k]; m = fmaxf(m, w[k]); }
        float s = 0.f;
        #pragma unroll
        for (int k = 0; k < KK; k++) { w[k] = expf(w[k] - m); s += w[k]; }
        float invs = 1.0f / s;
        #pragma unroll
        for (int k = 0; k < KK; k++) w[k] = MINW + (1.0f - MINW * KK) * (w[k] * invs);

        m = -1e30f;
        #pragma unroll
        for (int k = 0; k < KK; k++) { h[k] = uh[d * KK + k]; m = fmaxf(m, h[k]); }
        s = 0.f;
        #pragma unroll
        for (int k = 0; k < KK; k++) { h[k] = expf(h[k] - m); s += h[k]; }
        invs = 1.0f / s;
        #pragma unroll
        for (int k = 0; k < KK; k++) h[k] = MINH + (1.0f - MINH * KK) * (h[k] * invs);

        float cw[KK + 1], ch[KK + 1];
        cw[0] = -BOUND; ch[0] = -BOUND;
        float accw = 0.f, acch = 0.f;
        #pragma unroll
        for (int k = 1; k < KK; k++) {
            accw += w[k - 1]; cw[k] = fmaf(2.0f * BOUND, accw, -BOUND);
            acch += h[k - 1]; ch[k] = fmaf(2.0f * BOUND, acch, -BOUND);
        }
        cw[KK] = BOUND; ch[KK] = BOUND;

        float dv[KK + 1];
        dv[0] = 1.0f - MIND; dv[KK] = 1.0f - MIND;
        #pragma unroll
        for (int k = 1; k < KK; k++) {
            float v = ud[d * (KK - 1) + (k - 1)];
            dv[k] = MIND + fmaxf(v, 0.0f) + log1pf(expf(-fabsf(v)));
        }

        const int pos = ((d & 3) << 5) + (d >> 2);   // [c][lane] remap
        #pragma unroll
        for (int k = 0; k < KK; k++) {
            float W = cw[k + 1] - cw[k];
            float H = ch[k + 1] - ch[k];
            float invW = 1.0f / W;
            float del  = H * invW;
            float d0 = dv[k], d1 = dv[k + 1];
            float del2 = del * del;
            float* r = &sT[(k * DD + pos) * RSZ];
            r[0] = invW;
            r[1] = -cw[k] * invW;
            r[2] = ch[k];
            r[3] = H * del;
            r[4] = H * d0;
            r[5] = d0 + d1 - 2.0f * del;
            r[6] = del;
            r[7] = d1 * del2;
            r[8] = 2.0f * del * del2;
            r[9] = d0 * del2;
            r[10] = (k < KK - 1) ? (cw[k + 1] + EPS) : 0.0f;
            r[11] = 0.0f;
        }
    }
    __syncthreads();

    // ---- hoist thresholds for this lane's 4 dims into registers ----
    float th[4][KK - 1];
    #pragma unroll
    for (int c = 0; c < 4; c++) {
        #pragma unroll
        for (int k = 0; k < KK - 1; k++)
            th[c][k] = sT[(k * DD + (c << 5) + lane) * RSZ + 10];
    }

    const int row0 = (blockIdx.x * WARPS + warp) * RPW;

    #pragma unroll 2
    for (int rr = 0; rr < RPW; rr++) {
        const int row = row0 + rr;
        if (row >= BB) break;
        const float4 xv = *reinterpret_cast<const float4*>(x + (size_t)row * DD + (lane << 2));
        float xin[4] = {xv.x, xv.y, xv.z, xv.w};
        float uo4[4];
        float lsum = 0.f;

        #pragma unroll
        for (int c = 0; c < 4; c++) {
            const float xi = xin[c];
            const float xc = fminf(fmaxf(xi, -3.0f), 3.0f);
            const bool inside = (xc == xi);

            int k = 0;
            #pragma unroll
            for (int t = 0; t < KK - 1; t++) k += (xc >= th[c][t]);

            const float* r = &sT[(k * DD + (c << 5) + lane) * RSZ];
            const float4 A = *reinterpret_cast<const float4*>(r);
            const float4 Bv = *reinterpret_cast<const float4*>(r + 4);
            const float4 C = *reinterpret_cast<const float4*>(r + 8);

            const float theta = fmaf(xc, A.x, A.y);
            const float omt   = 1.0f - theta;
            const float th2   = theta * theta;
            const float t1m   = theta * omt;
            const float omt2  = omt * omt;

            const float num    = fmaf(A.w, th2, Bv.x * t1m);        // Hδθ² + Hd0·t1m
            const float den    = fmaf(Bv.y, t1m, Bv.z);             // e·t1m + δ
            const float invden = __fdividef(1.0f, den);
            float uo = fmaf(num, invden, A.z);

            const float dnum = fmaf(Bv.w, th2, fmaf(C.x, t1m, C.y * omt2));
            const float lad  = __logf(dnum * invden * invden);

            uo4[c] = inside ? uo : xi;
            lsum += inside ? lad : 0.0f;
        }

        float4 ov = make_float4(uo4[0], uo4[1], uo4[2], uo4[3]);
        *reinterpret_cast<float4*>(uout + (size_t)row * DD + (lane << 2)) = ov;

        #pragma unroll
        for (int off = 16; off; off >>= 1)
            lsum += __shfl_xor_sync(0xffffffffu, lsum, off);
        if (lane == 0) ldout[row] = lsum;
    }
}

extern "C" void kernel_launch(void* const* d_in, const int* in_sizes, int n_in,
                              void* d_out, int out_size) {
    const float* x  = (const float*)d_in[0];
    const float* uw = (const float*)d_in[1];
    const float* uh = (const float*)d_in[2];
    const float* ud = (const float*)d_in[3];
    float* out = (float*)d_out;

    spline_kernel<<<NBLOCKS, WARPS * 32>>>(
        x, uw, uh, ud, out, out + (size_t)BB * DD);
}